// round 5
// baseline (speedup 1.0000x reference)
#include <cuda_runtime.h>
#include <cstddef>

#define D 64
#define MAXN 100000

// Scratch buffers (no allocation allowed) -----------------------------------
__device__ float g_A[MAXN * D];
__device__ float g_B[MAXN * D];
__device__ float g_C[MAXN * D];
__device__ float g_M[MAXN * D];   // per-node messages
__device__ float g_AG[MAXN * D];  // aggregation

// ---------------------------------------------------------------------------
// packed f32x2 helpers (sm_103a: fma.rn.f32x2 doubles fp32 FMA throughput)
__device__ __forceinline__ unsigned long long fma2(unsigned long long a,
                                                   unsigned long long b,
                                                   unsigned long long c) {
    unsigned long long d;
    asm("fma.rn.f32x2 %0, %1, %2, %3;" : "=l"(d) : "l"(a), "l"(b), "l"(c));
    return d;
}
__device__ __forceinline__ unsigned long long pk2(float lo, float hi) {
    unsigned long long r;
    asm("mov.b64 %0, {%1, %2};" : "=l"(r)
        : "r"(__float_as_uint(lo)), "r"(__float_as_uint(hi)));
    return r;
}
__device__ __forceinline__ float2 unpk(unsigned long long p) {
    unsigned int lo, hi;
    asm("mov.b64 {%0, %1}, %2;" : "=r"(lo), "=r"(hi) : "l"(p));
    return make_float2(__uint_as_float(lo), __uint_as_float(hi));
}
union F4U { float4 v; unsigned long long u[2]; };

// ---------------------------------------------------------------------------
// out[i,:] = in[idx[i],:]  (row width 64)
__global__ __launch_bounds__(512) void gather_kernel(const float* __restrict__ in,
                                                     const int* __restrict__ idx,
                                                     float* __restrict__ out, int n) {
    int i = blockIdx.x * blockDim.x + threadIdx.x;
    if (i < n * 16) {
        int row = i >> 4;
        int c = i & 15;
        ((float4*)out)[i] = ((const float4*)in)[(size_t)idx[row] * 16 + c];
    }
}

// aggr[r[e],:] += msg[s[e],:]   via red.global.add.v4.f32
__global__ __launch_bounds__(256) void scatter_kernel(const float* __restrict__ msg,
                                                      const int* __restrict__ s,
                                                      const int* __restrict__ r,
                                                      float* __restrict__ aggr, long E16) {
    for (long i = (long)blockIdx.x * 256 + threadIdx.x; i < E16;
         i += (long)gridDim.x * 256) {
        int e = (int)(i >> 4);
        int c = (int)(i & 15);
        int se = __ldg(&s[e]);
        int re = __ldg(&r[e]);
        float4 v = __ldg((const float4*)msg + (size_t)se * 16 + c);
        float* dst = aggr + (size_t)re * 64 + c * 4;
        asm volatile("red.global.add.v4.f32 [%0], {%1,%2,%3,%4};"
                     :: "l"(dst), "f"(v.x), "f"(v.y), "f"(v.z), "f"(v.w)
                     : "memory");
    }
}

// ---------------------------------------------------------------------------
// Register-tiled 2-layer MLP with packed f32x2 FMA.
// out[row] = relu(X[row] @ W1 + b1) @ W2 + b2 (+skip[row])
// X rows: [in0 | in1] when IN==128, else in0 (row width IN).
// If rowidx != null, X rows are in0/in1[rowidx[row]]; out rows compact.
// If zero_out != null, zero_out rows of this tile are set to 0 (fused zeroing).
// 256 threads; tile = 64 rows x 64 cols; thread tile = 2 rows x 8 cols.
// ---------------------------------------------------------------------------
template <int IN>
__global__ __launch_bounds__(256) void mlp2_tiled(const float* __restrict__ in0,
                                                  const float* __restrict__ in1,
                                                  const int* __restrict__ rowidx,
                                                  const float* __restrict__ W1,
                                                  const float* __restrict__ b1,
                                                  const float* __restrict__ W2,
                                                  const float* __restrict__ b2,
                                                  const float* __restrict__ skip,
                                                  float* __restrict__ out,
                                                  float* __restrict__ zero_out, int n) {
    extern __shared__ __align__(16) float sm[];
    constexpr int XS = IN + 4;               // padded input row stride (floats)
    float* W1s = sm;                         // IN*64
    float* W2s = W1s + IN * 64;              // 64*64
    float* b1s = W2s + 64 * 64;              // 64
    float* b2s = b1s + 64;                   // 64
    float* inb = b2s + 64;                   // 64*XS
    float* yb  = inb + 64 * XS;              // 64*68

    const int t = threadIdx.x;
    for (int i = t; i < IN * 64; i += 256) W1s[i] = W1[i];
    for (int i = t; i < 64 * 64; i += 256) W2s[i] = W2[i];
    if (t < 64) { b1s[t] = b1[t]; b2s[t] = b2[t]; }
    __syncthreads();

    const int tc = t & 7;         // col group: j = tc*8
    const int tr = t >> 3;        // row group: rows tr*2, tr*2+1
    const int j = tc * 8;
    const int r0 = tr * 2;
    const int tiles = (n + 63) >> 6;

    for (int tile = blockIdx.x; tile < tiles; tile += gridDim.x) {
        const int base = tile * 64;
        // ---- stage X tile ----
        constexpr int C4 = IN / 4;
        for (int i = t; i < 64 * C4; i += 256) {
            int row = i / C4, c4 = i % C4, col = c4 * 4;
            int node = base + row;
            float4 v = make_float4(0.f, 0.f, 0.f, 0.f);
            if (node < n) {
                int src = rowidx ? rowidx[node] : node;
                if (IN == 128 && col >= 64)
                    v = *(const float4*)&in1[(size_t)src * 64 + (col - 64)];
                else
                    v = *(const float4*)&in0[(size_t)src * (IN == 128 ? 64 : IN) + col];
            }
            *(float4*)&inb[row * XS + col] = v;
        }
        __syncthreads();

        // ---- GEMM1: Y = relu(X @ W1 + b1) ----
        unsigned long long a[2][4];
        {
#pragma unroll
            for (int c = 0; c < 4; c++) {
                unsigned long long bi = pk2(b1s[j + 2 * c], b1s[j + 2 * c + 1]);
                a[0][c] = bi; a[1][c] = bi;
            }
        }
#pragma unroll
        for (int k = 0; k < IN; k += 4) {
            float4 xq0 = *(const float4*)&inb[(r0 + 0) * XS + k];
            float4 xq1 = *(const float4*)&inb[(r0 + 1) * XS + k];
#pragma unroll
            for (int kk = 0; kk < 4; kk++) {
                F4U w0, w1;
                w0.v = *(const float4*)&W1s[(k + kk) * 64 + j];
                w1.v = *(const float4*)&W1s[(k + kk) * 64 + j + 4];
                float x0 = ((const float*)&xq0)[kk];
                float x1 = ((const float*)&xq1)[kk];
                unsigned long long p0 = pk2(x0, x0);
                unsigned long long p1 = pk2(x1, x1);
                a[0][0] = fma2(p0, w0.u[0], a[0][0]);
                a[0][1] = fma2(p0, w0.u[1], a[0][1]);
                a[0][2] = fma2(p0, w1.u[0], a[0][2]);
                a[0][3] = fma2(p0, w1.u[1], a[0][3]);
                a[1][0] = fma2(p1, w0.u[0], a[1][0]);
                a[1][1] = fma2(p1, w0.u[1], a[1][1]);
                a[1][2] = fma2(p1, w1.u[0], a[1][2]);
                a[1][3] = fma2(p1, w1.u[1], a[1][3]);
            }
        }
#pragma unroll
        for (int i = 0; i < 2; i++) {
            float2 q0 = unpk(a[i][0]), q1 = unpk(a[i][1]);
            float2 q2 = unpk(a[i][2]), q3 = unpk(a[i][3]);
            float4 v0 = make_float4(fmaxf(q0.x, 0.f), fmaxf(q0.y, 0.f),
                                    fmaxf(q1.x, 0.f), fmaxf(q1.y, 0.f));
            float4 v1 = make_float4(fmaxf(q2.x, 0.f), fmaxf(q2.y, 0.f),
                                    fmaxf(q3.x, 0.f), fmaxf(q3.y, 0.f));
            *(float4*)&yb[(r0 + i) * 68 + j] = v0;
            *(float4*)&yb[(r0 + i) * 68 + j + 4] = v1;
        }
        __syncthreads();

        // ---- GEMM2: out = Y @ W2 + b2 (+skip) ----
        {
#pragma unroll
            for (int c = 0; c < 4; c++) {
                unsigned long long bi = pk2(b2s[j + 2 * c], b2s[j + 2 * c + 1]);
                a[0][c] = bi; a[1][c] = bi;
            }
        }
#pragma unroll
        for (int k = 0; k < 64; k += 4) {
            float4 xq0 = *(const float4*)&yb[(r0 + 0) * 68 + k];
            float4 xq1 = *(const float4*)&yb[(r0 + 1) * 68 + k];
#pragma unroll
            for (int kk = 0; kk < 4; kk++) {
                F4U w0, w1;
                w0.v = *(const float4*)&W2s[(k + kk) * 64 + j];
                w1.v = *(const float4*)&W2s[(k + kk) * 64 + j + 4];
                float x0 = ((const float*)&xq0)[kk];
                float x1 = ((const float*)&xq1)[kk];
                unsigned long long p0 = pk2(x0, x0);
                unsigned long long p1 = pk2(x1, x1);
                a[0][0] = fma2(p0, w0.u[0], a[0][0]);
                a[0][1] = fma2(p0, w0.u[1], a[0][1]);
                a[0][2] = fma2(p0, w1.u[0], a[0][2]);
                a[0][3] = fma2(p0, w1.u[1], a[0][3]);
                a[1][0] = fma2(p1, w0.u[0], a[1][0]);
                a[1][1] = fma2(p1, w0.u[1], a[1][1]);
                a[1][2] = fma2(p1, w1.u[0], a[1][2]);
                a[1][3] = fma2(p1, w1.u[1], a[1][3]);
            }
        }
#pragma unroll
        for (int i = 0; i < 2; i++) {
            int node = base + r0 + i;
            if (node < n) {
                float2 q0 = unpk(a[i][0]), q1 = unpk(a[i][1]);
                float2 q2 = unpk(a[i][2]), q3 = unpk(a[i][3]);
                float4 v0 = make_float4(q0.x, q0.y, q1.x, q1.y);
                float4 v1 = make_float4(q2.x, q2.y, q3.x, q3.y);
                if (skip) {
                    float4 s0 = *(const float4*)&skip[(size_t)node * 64 + j];
                    float4 s1 = *(const float4*)&skip[(size_t)node * 64 + j + 4];
                    v0.x += s0.x; v0.y += s0.y; v0.z += s0.z; v0.w += s0.w;
                    v1.x += s1.x; v1.y += s1.y; v1.z += s1.z; v1.w += s1.w;
                }
                *(float4*)&out[(size_t)node * 64 + j] = v0;
                *(float4*)&out[(size_t)node * 64 + j + 4] = v1;
                if (zero_out) {
                    float4 z = make_float4(0.f, 0.f, 0.f, 0.f);
                    *(float4*)&zero_out[(size_t)node * 64 + j] = z;
                    *(float4*)&zero_out[(size_t)node * 64 + j + 4] = z;
                }
            }
        }
        __syncthreads();
    }
}

// decode: out[n,2] = relu(h@Wd1+bd1)@Wd2+bd2
__global__ __launch_bounds__(512) void decode_kernel(const float* __restrict__ hin,
                                                     const float* __restrict__ W1,
                                                     const float* __restrict__ b1,
                                                     const float* __restrict__ W2,
                                                     const float* __restrict__ b2,
                                                     float* __restrict__ out, int n) {
    __shared__ __align__(16) float W1s[D * D];
    __shared__ __align__(16) float b1s[D];
    __shared__ __align__(16) float W2s[D * 2];
    __shared__ __align__(16) float b2s[4];
    __shared__ __align__(16) float inb[8][D];
    __shared__ __align__(16) float yb[8][D];
    int t = threadIdx.x;
    for (int i = t; i < D * D; i += 512) W1s[i] = W1[i];
    if (t < D) b1s[t] = b1[t];
    if (t < D * 2) W2s[t] = W2[t];
    if (t < 2) b2s[t] = b2[t];
    __syncthreads();
    int g = t >> 6, j = t & 63;
    for (long base = (long)blockIdx.x * 8; base < n; base += (long)gridDim.x * 8) {
        int node = (int)base + g;
        bool valid = node < n;
        if (valid) inb[g][j] = hin[(size_t)node * D + j];
        __syncthreads();
        if (valid) {
            float acc = b1s[j];
            const float4* h4 = (const float4*)&inb[g][0];
#pragma unroll
            for (int kk = 0; kk < 16; kk++) {
                float4 v = h4[kk];
                int k = kk * 4;
                acc += v.x * W1s[(k + 0) * D + j];
                acc += v.y * W1s[(k + 1) * D + j];
                acc += v.z * W1s[(k + 2) * D + j];
                acc += v.w * W1s[(k + 3) * D + j];
            }
            yb[g][j] = fmaxf(acc, 0.0f);
        }
        __syncthreads();
        if (valid && j < 2) {
            float acc = b2s[j];
#pragma unroll
            for (int k = 0; k < D; k++) acc += yb[g][k] * W2s[k * 2 + j];
            out[(size_t)node * 2 + j] = acc;
        }
        __syncthreads();
    }
}

// ---------------------------------------------------------------------------
static inline int mini(long a, long b) { return (int)(a < b ? a : b); }

template <int IN>
static constexpr size_t mlp2_smem() {
    return (size_t)(IN * 64 + 64 * 64 + 64 + 64 + 64 * (IN + 4) + 64 * 68) * sizeof(float);
}

extern "C" void kernel_launch(void* const* d_in, const int* in_sizes, int n_in,
                              void* d_out, int out_size) {
    const float* x   = (const float*)d_in[0];
    const float* We1 = (const float*)d_in[1];
    const float* be1 = (const float*)d_in[2];
    const float* We2 = (const float*)d_in[3];
    const float* be2 = (const float*)d_in[4];
    const float* Wm1 = (const float*)d_in[5];
    const float* bm1 = (const float*)d_in[6];
    const float* Wm2 = (const float*)d_in[7];
    const float* bm2 = (const float*)d_in[8];
    const float* Wn1 = (const float*)d_in[9];
    const float* bn1 = (const float*)d_in[10];
    const float* Wn2 = (const float*)d_in[11];
    const float* bn2 = (const float*)d_in[12];
    const float* Wd1 = (const float*)d_in[13];
    const float* bd1 = (const float*)d_in[14];
    const float* Wd2 = (const float*)d_in[15];
    const float* bd2 = (const float*)d_in[16];
    const int* s_f  = (const int*)d_in[17];
    const int* r_f  = (const int*)d_in[18];
    const int* s_ds = (const int*)d_in[19];
    const int* r_ds = (const int*)d_in[20];
    const int* s_p  = (const int*)d_in[21];
    const int* r_p  = (const int*)d_in[22];
    const int* s_us = (const int*)d_in[23];
    const int* r_us = (const int*)d_in[24];
    const int* uppool   = (const int*)d_in[25];
    const int* downpool = (const int*)d_in[26];

    int N   = in_sizes[0] / 16;
    int NP  = in_sizes[26];
    int E   = in_sizes[17];
    int EDS = in_sizes[19];
    int EP  = in_sizes[21];
    int EUS = in_sizes[23];
    float* out = (float*)d_out;

    float *A, *B, *C, *M, *AG;
    cudaGetSymbolAddress((void**)&A, g_A);
    cudaGetSymbolAddress((void**)&B, g_B);
    cudaGetSymbolAddress((void**)&C, g_C);
    cudaGetSymbolAddress((void**)&M, g_M);
    cudaGetSymbolAddress((void**)&AG, g_AG);

    static bool attr_done = false;
    if (!attr_done) {
        cudaFuncSetAttribute(mlp2_tiled<16>, cudaFuncAttributeMaxDynamicSharedMemorySize,
                             (int)mlp2_smem<16>());
        cudaFuncSetAttribute(mlp2_tiled<64>, cudaFuncAttributeMaxDynamicSharedMemorySize,
                             (int)mlp2_smem<64>());
        cudaFuncSetAttribute(mlp2_tiled<128>, cudaFuncAttributeMaxDynamicSharedMemorySize,
                             (int)mlp2_smem<128>());
        attr_done = true;
    }

    auto grid_for = [](int n) { return mini(((long)n + 63) / 64, 2048); };

    // one message-passing layer; node MLP optionally restricted to sel rows.
    // AG zeroing is fused into the message-MLP epilogue.
    auto mp = [&](int l, const float* hin, float* hout, const int* s, const int* r,
                  int Ecnt, int n, const float* skip, const int* sel, int nout) {
        mlp2_tiled<64><<<grid_for(n), 256, mlp2_smem<64>()>>>(
            hin, nullptr, nullptr, Wm1 + (size_t)l * D * D, bm1 + (size_t)l * D,
            Wm2 + (size_t)l * D * D, bm2 + (size_t)l * D, nullptr, M, AG, n);
        long E16 = (long)Ecnt * 16;
        scatter_kernel<<<mini((E16 + 255) / 256, 8192), 256>>>(M, s, r, AG, E16);
        mlp2_tiled<128><<<grid_for(nout), 256, mlp2_smem<128>()>>>(
            hin, AG, sel, Wn1 + (size_t)l * 128 * D, bn1 + (size_t)l * D,
            Wn2 + (size_t)l * D * D, bn2 + (size_t)l * D, skip, hout, nullptr, nout);
    };

    // encode
    mlp2_tiled<16><<<grid_for(N), 256, mlp2_smem<16>()>>>(
        x, nullptr, nullptr, We1, be1, We2, be2, nullptr, A, nullptr, N);
    // two fine MP layers
    mp(0, A, B, s_f, r_f, E, N, nullptr, nullptr, N);
    mp(1, B, C, s_f, r_f, E, N, nullptr, nullptr, N);
    // skip = C
    // downsample: gather h[uppool], MP on ds graph, node MLP only on downpool rows
    gather_kernel<<<(N * 16 + 511) / 512, 512>>>(C, uppool, A, N);
    mp(2, A, B, s_ds, r_ds, EDS, N, nullptr, downpool, NP);   // B = hp [NP]
    // bottleneck
    mp(3, B, A, s_p, r_p, EP, NP, nullptr, nullptr, NP);
    mp(4, A, B, s_p, r_p, EP, NP, nullptr, nullptr, NP);
    // upsample path: gather by downpool, MP on upsampling graph
    gather_kernel<<<(NP * 16 + 511) / 512, 512>>>(B, downpool, A, NP);
    mp(5, A, B, s_us, r_us, EUS, NP, nullptr, nullptr, NP);
    // scatter back to fine level via uppool gather
    gather_kernel<<<(N * 16 + 511) / 512, 512>>>(B, uppool, A, N);
    // decode MP layers with skip connections
    mp(6, A, B, s_f, r_f, E, N, C, nullptr, N);
    mp(7, B, A, s_f, r_f, E, N, C, nullptr, N);
    // decode head
    decode_kernel<<<mini(((long)N + 7) / 8, 4096), 512>>>(A, Wd1, bd1, Wd2, bd2, out, N);
}

// round 6
// speedup vs baseline: 1.6342x; 1.6342x over previous
#include <cuda_runtime.h>
#include <cstddef>

#define D 64
#define MAXN 100000

typedef unsigned long long u64;

// Scratch buffers (no allocation allowed) -----------------------------------
__device__ float g_A[MAXN * D];
__device__ float g_B[MAXN * D];
__device__ float g_C[MAXN * D];
__device__ float g_M[MAXN * D];   // per-node messages
__device__ float g_AG[MAXN * D];  // aggregation

// ---------------------------------------------------------------------------
// packed f32x2 helpers (sm_103a: fma.rn.f32x2 doubles fp32 FMA throughput)
__device__ __forceinline__ u64 fma2(u64 a, u64 b, u64 c) {
    u64 d;
    asm("fma.rn.f32x2 %0, %1, %2, %3;" : "=l"(d) : "l"(a), "l"(b), "l"(c));
    return d;
}
__device__ __forceinline__ u64 pk2(float lo, float hi) {
    u64 r;
    asm("mov.b64 %0, {%1, %2};" : "=l"(r)
        : "r"(__float_as_uint(lo)), "r"(__float_as_uint(hi)));
    return r;
}
__device__ __forceinline__ float2 unpk(u64 p) {
    unsigned int lo, hi;
    asm("mov.b64 {%0, %1}, %2;" : "=r"(lo), "=r"(hi) : "l"(p));
    return make_float2(__uint_as_float(lo), __uint_as_float(hi));
}
union F4U { float4 v; u64 u[2]; };

// ---------------------------------------------------------------------------
// out[i,:] = in[idx[i],:]  (row width 64)
__global__ __launch_bounds__(512) void gather_kernel(const float* __restrict__ in,
                                                     const int* __restrict__ idx,
                                                     float* __restrict__ out, int n) {
    int i = blockIdx.x * blockDim.x + threadIdx.x;
    if (i < n * 16) {
        int row = i >> 4;
        int c = i & 15;
        ((float4*)out)[i] = ((const float4*)in)[(size_t)idx[row] * 16 + c];
    }
}

// aggr[r[e],:] += msg[s[e],:]   via red.global.add.v4.f32
__global__ __launch_bounds__(256) void scatter_kernel(const float* __restrict__ msg,
                                                      const int* __restrict__ s,
                                                      const int* __restrict__ r,
                                                      float* __restrict__ aggr, long E16) {
    for (long i = (long)blockIdx.x * 256 + threadIdx.x; i < E16;
         i += (long)gridDim.x * 256) {
        int e = (int)(i >> 4);
        int c = (int)(i & 15);
        int se = __ldg(&s[e]);
        int re = __ldg(&r[e]);
        float4 v = __ldg((const float4*)msg + (size_t)se * 16 + c);
        float* dst = aggr + (size_t)re * 64 + c * 4;
        asm volatile("red.global.add.v4.f32 [%0], {%1,%2,%3,%4};"
                     :: "l"(dst), "f"(v.x), "f"(v.y), "f"(v.z), "f"(v.w)
                     : "memory");
    }
}

// ---------------------------------------------------------------------------
// Register-tiled 2-layer MLP, f32x2-FMA with K-paired weights in shared.
// out[row] = relu(X[row] @ W1 + b1) @ W2 + b2 (+skip[row])
// X rows: [in0 | in1] when IN==128, else in0 (row width IN).
// If rowidx != null, X rows are in0/in1[rowidx[row]]; out rows compact.
// If zero_out != null, zero_out rows of this tile are set to 0 (fused zeroing).
// 256 threads; tile = 64 rows x 64 cols; thread tile = 4 rows x 4 cols,
// cols = {2tc, 2tc+1, 2tc+32, 2tc+33} (16B-stride weight LDS, conflict-free).
// Accumulator b64 halves hold even-k / odd-k partial sums (x pairs come free
// from the float4 row load; weights pre-paired in SMEM). lo+hi at the end.
// ---------------------------------------------------------------------------
template <int IN>
__global__ __launch_bounds__(256) void mlp2_tiled(const float* __restrict__ in0,
                                                  const float* __restrict__ in1,
                                                  const int* __restrict__ rowidx,
                                                  const float* __restrict__ W1,
                                                  const float* __restrict__ b1,
                                                  const float* __restrict__ W2,
                                                  const float* __restrict__ b2,
                                                  const float* __restrict__ skip,
                                                  float* __restrict__ out,
                                                  float* __restrict__ zero_out, int n) {
    extern __shared__ __align__(16) float sm[];
    constexpr int XS = IN + 4;                     // padded input row stride
    u64* W1p = (u64*)sm;                           // (IN/2)*64 u64
    u64* W2p = W1p + (IN / 2) * 64;                // 32*64 u64
    float* b1s = (float*)(W2p + 32 * 64);          // 64
    float* b2s = b1s + 64;                         // 64
    float* inb = b2s + 64;                         // 64*XS
    float* yb  = inb + 64 * XS;                    // 64*68

    const int t = threadIdx.x;
    // stage K-paired weights: Wp[k2][c] = (W[2k2][c], W[2k2+1][c])
    for (int i = t; i < (IN / 2) * 64; i += 256) {
        int k2 = i >> 6, c = i & 63;
        W1p[i] = pk2(W1[(2 * k2) * 64 + c], W1[(2 * k2 + 1) * 64 + c]);
    }
    for (int i = t; i < 32 * 64; i += 256) {
        int k2 = i >> 6, c = i & 63;
        W2p[i] = pk2(W2[(2 * k2) * 64 + c], W2[(2 * k2 + 1) * 64 + c]);
    }
    if (t < 64) { b1s[t] = b1[t]; b2s[t] = b2[t]; }
    __syncthreads();

    const int tc = t & 15;        // col group
    const int tr = t >> 4;        // row group (rows tr*4 .. tr*4+3)
    const int c0 = tc * 2;        // cols c0, c0+1, c0+32, c0+33
    const int c2 = c0 + 32;
    const int tiles = (n + 63) >> 6;

    for (int tile = blockIdx.x; tile < tiles; tile += gridDim.x) {
        const int base = tile * 64;
        // ---- stage X tile ----
        constexpr int C4 = IN / 4;
        for (int i = t; i < 64 * C4; i += 256) {
            int row = i / C4, c4 = i % C4, col = c4 * 4;
            int node = base + row;
            float4 v = make_float4(0.f, 0.f, 0.f, 0.f);
            if (node < n) {
                int src = rowidx ? rowidx[node] : node;
                if (IN == 128 && col >= 64)
                    v = *(const float4*)&in1[(size_t)src * 64 + (col - 64)];
                else
                    v = *(const float4*)&in0[(size_t)src * (IN == 128 ? 64 : IN) + col];
            }
            *(float4*)&inb[row * XS + col] = v;
        }
        __syncthreads();

        // ---- GEMM1: Y = relu(X @ W1 + b1) ----
        u64 a[4][4];
#pragma unroll
        for (int i = 0; i < 4; i++) {
            a[i][0] = pk2(b1s[c0], 0.f);
            a[i][1] = pk2(b1s[c0 + 1], 0.f);
            a[i][2] = pk2(b1s[c2], 0.f);
            a[i][3] = pk2(b1s[c2 + 1], 0.f);
        }
#pragma unroll 8
        for (int k = 0; k < IN; k += 4) {
            F4U xq[4];
#pragma unroll
            for (int i = 0; i < 4; i++)
                xq[i].v = *(const float4*)&inb[(tr * 4 + i) * XS + k];
#pragma unroll
            for (int kk2 = 0; kk2 < 2; kk2++) {
                ulonglong2 wA = *(const ulonglong2*)&W1p[(k / 2 + kk2) * 64 + c0];
                ulonglong2 wB = *(const ulonglong2*)&W1p[(k / 2 + kk2) * 64 + c2];
#pragma unroll
                for (int i = 0; i < 4; i++) {
                    u64 xp = xq[i].u[kk2];
                    a[i][0] = fma2(xp, wA.x, a[i][0]);
                    a[i][1] = fma2(xp, wA.y, a[i][1]);
                    a[i][2] = fma2(xp, wB.x, a[i][2]);
                    a[i][3] = fma2(xp, wB.y, a[i][3]);
                }
            }
        }
#pragma unroll
        for (int i = 0; i < 4; i++) {
            float2 q0 = unpk(a[i][0]), q1 = unpk(a[i][1]);
            float2 q2 = unpk(a[i][2]), q3 = unpk(a[i][3]);
            float2 vA = make_float2(fmaxf(q0.x + q0.y, 0.f), fmaxf(q1.x + q1.y, 0.f));
            float2 vB = make_float2(fmaxf(q2.x + q2.y, 0.f), fmaxf(q3.x + q3.y, 0.f));
            *(float2*)&yb[(tr * 4 + i) * 68 + c0] = vA;
            *(float2*)&yb[(tr * 4 + i) * 68 + c2] = vB;
        }
        __syncthreads();

        // ---- GEMM2: out = Y @ W2 + b2 (+skip) ----
#pragma unroll
        for (int i = 0; i < 4; i++) {
            a[i][0] = pk2(b2s[c0], 0.f);
            a[i][1] = pk2(b2s[c0 + 1], 0.f);
            a[i][2] = pk2(b2s[c2], 0.f);
            a[i][3] = pk2(b2s[c2 + 1], 0.f);
        }
#pragma unroll 8
        for (int k = 0; k < 64; k += 4) {
            F4U xq[4];
#pragma unroll
            for (int i = 0; i < 4; i++)
                xq[i].v = *(const float4*)&yb[(tr * 4 + i) * 68 + k];
#pragma unroll
            for (int kk2 = 0; kk2 < 2; kk2++) {
                ulonglong2 wA = *(const ulonglong2*)&W2p[(k / 2 + kk2) * 64 + c0];
                ulonglong2 wB = *(const ulonglong2*)&W2p[(k / 2 + kk2) * 64 + c2];
#pragma unroll
                for (int i = 0; i < 4; i++) {
                    u64 xp = xq[i].u[kk2];
                    a[i][0] = fma2(xp, wA.x, a[i][0]);
                    a[i][1] = fma2(xp, wA.y, a[i][1]);
                    a[i][2] = fma2(xp, wB.x, a[i][2]);
                    a[i][3] = fma2(xp, wB.y, a[i][3]);
                }
            }
        }
#pragma unroll
        for (int i = 0; i < 4; i++) {
            int node = base + tr * 4 + i;
            if (node < n) {
                float2 q0 = unpk(a[i][0]), q1 = unpk(a[i][1]);
                float2 q2 = unpk(a[i][2]), q3 = unpk(a[i][3]);
                float2 vA = make_float2(q0.x + q0.y, q1.x + q1.y);
                float2 vB = make_float2(q2.x + q2.y, q3.x + q3.y);
                if (skip) {
                    float2 sA = *(const float2*)&skip[(size_t)node * 64 + c0];
                    float2 sB = *(const float2*)&skip[(size_t)node * 64 + c2];
                    vA.x += sA.x; vA.y += sA.y;
                    vB.x += sB.x; vB.y += sB.y;
                }
                *(float2*)&out[(size_t)node * 64 + c0] = vA;
                *(float2*)&out[(size_t)node * 64 + c2] = vB;
                if (zero_out) {
                    float2 z = make_float2(0.f, 0.f);
                    *(float2*)&zero_out[(size_t)node * 64 + c0] = z;
                    *(float2*)&zero_out[(size_t)node * 64 + c2] = z;
                }
            }
        }
        __syncthreads();
    }
}

// decode: out[n,2] = relu(h@Wd1+bd1)@Wd2+bd2
__global__ __launch_bounds__(512) void decode_kernel(const float* __restrict__ hin,
                                                     const float* __restrict__ W1,
                                                     const float* __restrict__ b1,
                                                     const float* __restrict__ W2,
                                                     const float* __restrict__ b2,
                                                     float* __restrict__ out, int n) {
    __shared__ __align__(16) float W1s[D * D];
    __shared__ __align__(16) float b1s[D];
    __shared__ __align__(16) float W2s[D * 2];
    __shared__ __align__(16) float b2s[4];
    __shared__ __align__(16) float inb[8][D];
    __shared__ __align__(16) float yb[8][D];
    int t = threadIdx.x;
    for (int i = t; i < D * D; i += 512) W1s[i] = W1[i];
    if (t < D) b1s[t] = b1[t];
    if (t < D * 2) W2s[t] = W2[t];
    if (t < 2) b2s[t] = b2[t];
    __syncthreads();
    int g = t >> 6, j = t & 63;
    for (long base = (long)blockIdx.x * 8; base < n; base += (long)gridDim.x * 8) {
        int node = (int)base + g;
        bool valid = node < n;
        if (valid) inb[g][j] = hin[(size_t)node * D + j];
        __syncthreads();
        if (valid) {
            float acc = b1s[j];
            const float4* h4 = (const float4*)&inb[g][0];
#pragma unroll
            for (int kk = 0; kk < 16; kk++) {
                float4 v = h4[kk];
                int k = kk * 4;
                acc += v.x * W1s[(k + 0) * D + j];
                acc += v.y * W1s[(k + 1) * D + j];
                acc += v.z * W1s[(k + 2) * D + j];
                acc += v.w * W1s[(k + 3) * D + j];
            }
            yb[g][j] = fmaxf(acc, 0.0f);
        }
        __syncthreads();
        if (valid && j < 2) {
            float acc = b2s[j];
#pragma unroll
            for (int k = 0; k < D; k++) acc += yb[g][k] * W2s[k * 2 + j];
            out[(size_t)node * 2 + j] = acc;
        }
        __syncthreads();
    }
}

// ---------------------------------------------------------------------------
static inline int mini(long a, long b) { return (int)(a < b ? a : b); }

template <int IN>
static constexpr size_t mlp2_smem() {
    return (size_t)(IN * 64 + 64 * 64 + 64 + 64 + 64 * (IN + 4) + 64 * 68) * sizeof(float);
}

extern "C" void kernel_launch(void* const* d_in, const int* in_sizes, int n_in,
                              void* d_out, int out_size) {
    const float* x   = (const float*)d_in[0];
    const float* We1 = (const float*)d_in[1];
    const float* be1 = (const float*)d_in[2];
    const float* We2 = (const float*)d_in[3];
    const float* be2 = (const float*)d_in[4];
    const float* Wm1 = (const float*)d_in[5];
    const float* bm1 = (const float*)d_in[6];
    const float* Wm2 = (const float*)d_in[7];
    const float* bm2 = (const float*)d_in[8];
    const float* Wn1 = (const float*)d_in[9];
    const float* bn1 = (const float*)d_in[10];
    const float* Wn2 = (const float*)d_in[11];
    const float* bn2 = (const float*)d_in[12];
    const float* Wd1 = (const float*)d_in[13];
    const float* bd1 = (const float*)d_in[14];
    const float* Wd2 = (const float*)d_in[15];
    const float* bd2 = (const float*)d_in[16];
    const int* s_f  = (const int*)d_in[17];
    const int* r_f  = (const int*)d_in[18];
    const int* s_ds = (const int*)d_in[19];
    const int* r_ds = (const int*)d_in[20];
    const int* s_p  = (const int*)d_in[21];
    const int* r_p  = (const int*)d_in[22];
    const int* s_us = (const int*)d_in[23];
    const int* r_us = (const int*)d_in[24];
    const int* uppool   = (const int*)d_in[25];
    const int* downpool = (const int*)d_in[26];

    int N   = in_sizes[0] / 16;
    int NP  = in_sizes[26];
    int E   = in_sizes[17];
    int EDS = in_sizes[19];
    int EP  = in_sizes[21];
    int EUS = in_sizes[23];
    float* out = (float*)d_out;

    float *A, *B, *C, *M, *AG;
    cudaGetSymbolAddress((void**)&A, g_A);
    cudaGetSymbolAddress((void**)&B, g_B);
    cudaGetSymbolAddress((void**)&C, g_C);
    cudaGetSymbolAddress((void**)&M, g_M);
    cudaGetSymbolAddress((void**)&AG, g_AG);

    static bool attr_done = false;
    if (!attr_done) {
        cudaFuncSetAttribute(mlp2_tiled<16>, cudaFuncAttributeMaxDynamicSharedMemorySize,
                             (int)mlp2_smem<16>());
        cudaFuncSetAttribute(mlp2_tiled<64>, cudaFuncAttributeMaxDynamicSharedMemorySize,
                             (int)mlp2_smem<64>());
        cudaFuncSetAttribute(mlp2_tiled<128>, cudaFuncAttributeMaxDynamicSharedMemorySize,
                             (int)mlp2_smem<128>());
        attr_done = true;
    }

    auto grid_for = [](int n) { return mini(((long)n + 63) / 64, 2048); };

    // one message-passing layer; node MLP optionally restricted to sel rows.
    // AG zeroing is fused into the message-MLP epilogue.
    auto mp = [&](int l, const float* hin, float* hout, const int* s, const int* r,
                  int Ecnt, int n, const float* skip, const int* sel, int nout) {
        mlp2_tiled<64><<<grid_for(n), 256, mlp2_smem<64>()>>>(
            hin, nullptr, nullptr, Wm1 + (size_t)l * D * D, bm1 + (size_t)l * D,
            Wm2 + (size_t)l * D * D, bm2 + (size_t)l * D, nullptr, M, AG, n);
        long E16 = (long)Ecnt * 16;
        scatter_kernel<<<mini((E16 + 255) / 256, 8192), 256>>>(M, s, r, AG, E16);
        mlp2_tiled<128><<<grid_for(nout), 256, mlp2_smem<128>()>>>(
            hin, AG, sel, Wn1 + (size_t)l * 128 * D, bn1 + (size_t)l * D,
            Wn2 + (size_t)l * D * D, bn2 + (size_t)l * D, skip, hout, nullptr, nout);
    };

    // encode
    mlp2_tiled<16><<<grid_for(N), 256, mlp2_smem<16>()>>>(
        x, nullptr, nullptr, We1, be1, We2, be2, nullptr, A, nullptr, N);
    // two fine MP layers
    mp(0, A, B, s_f, r_f, E, N, nullptr, nullptr, N);
    mp(1, B, C, s_f, r_f, E, N, nullptr, nullptr, N);
    // skip = C
    // downsample: gather h[uppool], MP on ds graph, node MLP only on downpool rows
    gather_kernel<<<(N * 16 + 511) / 512, 512>>>(C, uppool, A, N);
    mp(2, A, B, s_ds, r_ds, EDS, N, nullptr, downpool, NP);   // B = hp [NP]
    // bottleneck
    mp(3, B, A, s_p, r_p, EP, NP, nullptr, nullptr, NP);
    mp(4, A, B, s_p, r_p, EP, NP, nullptr, nullptr, NP);
    // upsample path: gather by downpool, MP on upsampling graph
    gather_kernel<<<(NP * 16 + 511) / 512, 512>>>(B, downpool, A, NP);
    mp(5, A, B, s_us, r_us, EUS, NP, nullptr, nullptr, NP);
    // scatter back to fine level via uppool gather
    gather_kernel<<<(N * 16 + 511) / 512, 512>>>(B, uppool, A, N);
    // decode MP layers with skip connections
    mp(6, A, B, s_f, r_f, E, N, C, nullptr, N);
    mp(7, B, A, s_f, r_f, E, N, C, nullptr, N);
    // decode head
    decode_kernel<<<mini(((long)N + 7) / 8, 4096), 512>>>(A, Wd1, bd1, Wd2, bd2, out, N);
}

// round 8
// speedup vs baseline: 1.9326x; 1.1826x over previous
#include <cuda_runtime.h>
#include <cstddef>

#define D 64
#define MAXN 100000

typedef unsigned long long u64;

// Scratch buffers (no allocation allowed) -----------------------------------
__device__ float g_A[MAXN * D];
__device__ float g_B[MAXN * D];
__device__ float g_C[MAXN * D];
__device__ float g_M[MAXN * D];   // per-node messages
__device__ float g_AG[MAXN * D];  // aggregation

// ---------------------------------------------------------------------------
// packed f32x2 helpers (sm_103a: fma.rn.f32x2 doubles fp32 FMA throughput)
__device__ __forceinline__ u64 fma2(u64 a, u64 b, u64 c) {
    u64 d;
    asm("fma.rn.f32x2 %0, %1, %2, %3;" : "=l"(d) : "l"(a), "l"(b), "l"(c));
    return d;
}
__device__ __forceinline__ u64 pk2(float lo, float hi) {
    u64 r;
    asm("mov.b64 %0, {%1, %2};" : "=l"(r)
        : "r"(__float_as_uint(lo)), "r"(__float_as_uint(hi)));
    return r;
}
__device__ __forceinline__ float2 unpk(u64 p) {
    unsigned int lo, hi;
    asm("mov.b64 {%0, %1}, %2;" : "=r"(lo), "=r"(hi) : "l"(p));
    return make_float2(__uint_as_float(lo), __uint_as_float(hi));
}
union F4U { float4 v; u64 u[2]; };

// ---------------------------------------------------------------------------
// out[i,:] = in[idx[i],:]  (row width 64)
__global__ __launch_bounds__(512) void gather_kernel(const float* __restrict__ in,
                                                     const int* __restrict__ idx,
                                                     float* __restrict__ out, int n) {
    int i = blockIdx.x * blockDim.x + threadIdx.x;
    if (i < n * 16) {
        int row = i >> 4;
        int c = i & 15;
        ((float4*)out)[i] = ((const float4*)in)[(size_t)idx[row] * 16 + c];
    }
}

// aggr[r[e],:] += msg[s[e],:]   via red.global.add.v4.f32
__global__ __launch_bounds__(256) void scatter_kernel(const float* __restrict__ msg,
                                                      const int* __restrict__ s,
                                                      const int* __restrict__ r,
                                                      float* __restrict__ aggr, long E16) {
    for (long i = (long)blockIdx.x * 256 + threadIdx.x; i < E16;
         i += (long)gridDim.x * 256) {
        int e = (int)(i >> 4);
        int c = (int)(i & 15);
        int se = __ldg(&s[e]);
        int re = __ldg(&r[e]);
        float4 v = __ldg((const float4*)msg + (size_t)se * 16 + c);
        float* dst = aggr + (size_t)re * 64 + c * 4;
        asm volatile("red.global.add.v4.f32 [%0], {%1,%2,%3,%4};"
                     :: "l"(dst), "f"(v.x), "f"(v.y), "f"(v.z), "f"(v.w)
                     : "memory");
    }
}

// ---------------------------------------------------------------------------
// Register-tiled 2-layer MLP, f32x2-FMA, K-paired weights, low-smem (~50KB)
// for 4 blocks/SM.  out[row] = relu(X[row]@W1+b1)@W2+b2 (+skip[row]).
// X rows: [in0 | in1] when IN==128 (processed as two 64-col halves reusing
// one staging buffer), else in0 (row width IN). The X buffer is re-used for
// Y between GEMM1 and GEMM2 (sync-guarded). W1 (or its active half) lives in
// one 32x64-u64 buffer, restaged per half.
// If rowidx != null, X rows are in0/in1[rowidx[row]]; out rows compact.
// If zero_out != null, those rows of zero_out are zeroed (fused zeroing).
// 256 threads; tile = 64 rows x 64 cols; thread tile = 4 rows x 4 cols,
// cols {2tc, 2tc+1, 2tc+32, 2tc+33}; accumulator b64 halves = even/odd k.
// ---------------------------------------------------------------------------
template <int IN>
__global__ __launch_bounds__(256, 4) void mlp2_tiled(const float* __restrict__ in0,
                                                     const float* __restrict__ in1,
                                                     const int* __restrict__ rowidx,
                                                     const float* __restrict__ W1,
                                                     const float* __restrict__ b1,
                                                     const float* __restrict__ W2,
                                                     const float* __restrict__ b2,
                                                     const float* __restrict__ skip,
                                                     float* __restrict__ out,
                                                     float* __restrict__ zero_out, int n) {
    extern __shared__ __align__(16) float sm[];
    u64* Wp  = (u64*)sm;                           // 32*64 u64: W1 (or half)
    u64* W2p = Wp + 32 * 64;                       // 32*64 u64
    float* b1s = (float*)(W2p + 32 * 64);          // 64
    float* b2s = b1s + 64;                         // 64
    float* xy  = b2s + 64;                         // 64*68 floats (X half / Y)

    const int t = threadIdx.x;
    constexpr int XC = (IN < 64) ? IN : 64;        // X cols staged per phase
    constexpr int NH = (IN == 128) ? 2 : 1;        // halves

    // stage W2 pairs + biases once
    for (int i = t; i < 32 * 64; i += 256) {
        int k2 = i >> 6, c = i & 63;
        W2p[i] = pk2(W2[(2 * k2) * 64 + c], W2[(2 * k2 + 1) * 64 + c]);
    }
    if (t < 64) { b1s[t] = b1[t]; b2s[t] = b2[t]; }
    __syncthreads();   // b1s/b2s/W2p visible before ANY use (fixes R7 race)

    const int tc = t & 15;
    const int tr = t >> 4;
    const int c0 = tc * 2, c2 = c0 + 32;
    const int r0 = tr * 4;
    const int tiles = (n + 63) >> 6;

    for (int tile = blockIdx.x; tile < tiles; tile += gridDim.x) {
        const int base = tile * 64;

        u64 a[4][4];
#pragma unroll
        for (int i = 0; i < 4; i++) {
            a[i][0] = pk2(b1s[c0], 0.f);
            a[i][1] = pk2(b1s[c0 + 1], 0.f);
            a[i][2] = pk2(b1s[c2], 0.f);
            a[i][3] = pk2(b1s[c2 + 1], 0.f);
        }

#pragma unroll
        for (int h = 0; h < NH; h++) {
            // stage W1 half (K-paired): whole W1 when IN<=64
            for (int i = t; i < (XC / 2) * 64; i += 256) {
                int k2 = i >> 6, c = i & 63;
                const float* Ws = W1 + h * 64 * 64;
                Wp[i] = pk2(Ws[(2 * k2) * 64 + c], Ws[(2 * k2 + 1) * 64 + c]);
            }
            // stage X columns for this half
            constexpr int C4 = XC / 4;
            for (int i = t; i < 64 * C4; i += 256) {
                int row = i / C4, col = (i % C4) * 4;
                int node = base + row;
                float4 v = make_float4(0.f, 0.f, 0.f, 0.f);
                if (node < n) {
                    int src = rowidx ? rowidx[node] : node;
                    const float* p = (h == 0) ? in0 : in1;
                    v = *(const float4*)&p[(size_t)src * XC + col];
                }
                *(float4*)&xy[row * 68 + col] = v;
            }
            __syncthreads();
            // accumulate over this half's K
#pragma unroll 8
            for (int k = 0; k < XC; k += 4) {
                F4U xq[4];
#pragma unroll
                for (int i = 0; i < 4; i++)
                    xq[i].v = *(const float4*)&xy[(r0 + i) * 68 + k];
#pragma unroll
                for (int kk2 = 0; kk2 < 2; kk2++) {
                    ulonglong2 wA = *(const ulonglong2*)&Wp[(k / 2 + kk2) * 64 + c0];
                    ulonglong2 wB = *(const ulonglong2*)&Wp[(k / 2 + kk2) * 64 + c2];
#pragma unroll
                    for (int i = 0; i < 4; i++) {
                        u64 xp = xq[i].u[kk2];
                        a[i][0] = fma2(xp, wA.x, a[i][0]);
                        a[i][1] = fma2(xp, wA.y, a[i][1]);
                        a[i][2] = fma2(xp, wB.x, a[i][2]);
                        a[i][3] = fma2(xp, wB.y, a[i][3]);
                    }
                }
            }
            __syncthreads();   // all reads of xy/Wp done before overwrite
        }

        // relu + write Y into xy (aliased, safe after sync)
#pragma unroll
        for (int i = 0; i < 4; i++) {
            float2 q0 = unpk(a[i][0]), q1 = unpk(a[i][1]);
            float2 q2 = unpk(a[i][2]), q3 = unpk(a[i][3]);
            float2 vA = make_float2(fmaxf(q0.x + q0.y, 0.f), fmaxf(q1.x + q1.y, 0.f));
            float2 vB = make_float2(fmaxf(q2.x + q2.y, 0.f), fmaxf(q3.x + q3.y, 0.f));
            *(float2*)&xy[(r0 + i) * 68 + c0] = vA;
            *(float2*)&xy[(r0 + i) * 68 + c2] = vB;
        }
        __syncthreads();

        // ---- GEMM2: out = Y @ W2 + b2 (+skip) ----
#pragma unroll
        for (int i = 0; i < 4; i++) {
            a[i][0] = pk2(b2s[c0], 0.f);
            a[i][1] = pk2(b2s[c0 + 1], 0.f);
            a[i][2] = pk2(b2s[c2], 0.f);
            a[i][3] = pk2(b2s[c2 + 1], 0.f);
        }
#pragma unroll 8
        for (int k = 0; k < 64; k += 4) {
            F4U xq[4];
#pragma unroll
            for (int i = 0; i < 4; i++)
                xq[i].v = *(const float4*)&xy[(r0 + i) * 68 + k];
#pragma unroll
            for (int kk2 = 0; kk2 < 2; kk2++) {
                ulonglong2 wA = *(const ulonglong2*)&W2p[(k / 2 + kk2) * 64 + c0];
                ulonglong2 wB = *(const ulonglong2*)&W2p[(k / 2 + kk2) * 64 + c2];
#pragma unroll
                for (int i = 0; i < 4; i++) {
                    u64 xp = xq[i].u[kk2];
                    a[i][0] = fma2(xp, wA.x, a[i][0]);
                    a[i][1] = fma2(xp, wA.y, a[i][1]);
                    a[i][2] = fma2(xp, wB.x, a[i][2]);
                    a[i][3] = fma2(xp, wB.y, a[i][3]);
                }
            }
        }
#pragma unroll
        for (int i = 0; i < 4; i++) {
            int node = base + r0 + i;
            if (node < n) {
                float2 q0 = unpk(a[i][0]), q1 = unpk(a[i][1]);
                float2 q2 = unpk(a[i][2]), q3 = unpk(a[i][3]);
                float2 vA = make_float2(q0.x + q0.y, q1.x + q1.y);
                float2 vB = make_float2(q2.x + q2.y, q3.x + q3.y);
                if (skip) {
                    float2 sA = *(const float2*)&skip[(size_t)node * 64 + c0];
                    float2 sB = *(const float2*)&skip[(size_t)node * 64 + c2];
                    vA.x += sA.x; vA.y += sA.y;
                    vB.x += sB.x; vB.y += sB.y;
                }
                *(float2*)&out[(size_t)node * 64 + c0] = vA;
                *(float2*)&out[(size_t)node * 64 + c2] = vB;
                if (zero_out) {
                    float2 z = make_float2(0.f, 0.f);
                    *(float2*)&zero_out[(size_t)node * 64 + c0] = z;
                    *(float2*)&zero_out[(size_t)node * 64 + c2] = z;
                }
            }
        }
        __syncthreads();   // xy reads done before next tile overwrites
    }
}

// decode: out[n,2] = relu(h@Wd1+bd1)@Wd2+bd2
__global__ __launch_bounds__(512) void decode_kernel(const float* __restrict__ hin,
                                                     const float* __restrict__ W1,
                                                     const float* __restrict__ b1,
                                                     const float* __restrict__ W2,
                                                     const float* __restrict__ b2,
                                                     float* __restrict__ out, int n) {
    __shared__ __align__(16) float W1s[D * D];
    __shared__ __align__(16) float b1s[D];
    __shared__ __align__(16) float W2s[D * 2];
    __shared__ __align__(16) float b2s[4];
    __shared__ __align__(16) float inb[8][D];
    __shared__ __align__(16) float yb[8][D];
    int t = threadIdx.x;
    for (int i = t; i < D * D; i += 512) W1s[i] = W1[i];
    if (t < D) b1s[t] = b1[t];
    if (t < D * 2) W2s[t] = W2[t];
    if (t < 2) b2s[t] = b2[t];
    __syncthreads();
    int g = t >> 6, j = t & 63;
    for (long base = (long)blockIdx.x * 8; base < n; base += (long)gridDim.x * 8) {
        int node = (int)base + g;
        bool valid = node < n;
        if (valid) inb[g][j] = hin[(size_t)node * D + j];
        __syncthreads();
        if (valid) {
            float acc = b1s[j];
            const float4* h4 = (const float4*)&inb[g][0];
#pragma unroll
            for (int kk = 0; kk < 16; kk++) {
                float4 v = h4[kk];
                int k = kk * 4;
                acc += v.x * W1s[(k + 0) * D + j];
                acc += v.y * W1s[(k + 1) * D + j];
                acc += v.z * W1s[(k + 2) * D + j];
                acc += v.w * W1s[(k + 3) * D + j];
            }
            yb[g][j] = fmaxf(acc, 0.0f);
        }
        __syncthreads();
        if (valid && j < 2) {
            float acc = b2s[j];
#pragma unroll
            for (int k = 0; k < D; k++) acc += yb[g][k] * W2s[k * 2 + j];
            out[(size_t)node * 2 + j] = acc;
        }
        __syncthreads();
    }
}

// ---------------------------------------------------------------------------
static inline int mini(long a, long b) { return (int)(a < b ? a : b); }

static constexpr size_t MLP_SMEM =
    (size_t)(32 * 64 * 8) * 2 + 128 * 4 + 64 * 68 * 4;   // ~49.5 KB

extern "C" void kernel_launch(void* const* d_in, const int* in_sizes, int n_in,
                              void* d_out, int out_size) {
    const float* x   = (const float*)d_in[0];
    const float* We1 = (const float*)d_in[1];
    const float* be1 = (const float*)d_in[2];
    const float* We2 = (const float*)d_in[3];
    const float* be2 = (const float*)d_in[4];
    const float* Wm1 = (const float*)d_in[5];
    const float* bm1 = (const float*)d_in[6];
    const float* Wm2 = (const float*)d_in[7];
    const float* bm2 = (const float*)d_in[8];
    const float* Wn1 = (const float*)d_in[9];
    const float* bn1 = (const float*)d_in[10];
    const float* Wn2 = (const float*)d_in[11];
    const float* bn2 = (const float*)d_in[12];
    const float* Wd1 = (const float*)d_in[13];
    const float* bd1 = (const float*)d_in[14];
    const float* Wd2 = (const float*)d_in[15];
    const float* bd2 = (const float*)d_in[16];
    const int* s_f  = (const int*)d_in[17];
    const int* r_f  = (const int*)d_in[18];
    const int* s_ds = (const int*)d_in[19];
    const int* r_ds = (const int*)d_in[20];
    const int* s_p  = (const int*)d_in[21];
    const int* r_p  = (const int*)d_in[22];
    const int* s_us = (const int*)d_in[23];
    const int* r_us = (const int*)d_in[24];
    const int* uppool   = (const int*)d_in[25];
    const int* downpool = (const int*)d_in[26];

    int N   = in_sizes[0] / 16;
    int NP  = in_sizes[26];
    int E   = in_sizes[17];
    int EDS = in_sizes[19];
    int EP  = in_sizes[21];
    int EUS = in_sizes[23];
    float* out = (float*)d_out;

    float *A, *B, *C, *M, *AG;
    cudaGetSymbolAddress((void**)&A, g_A);
    cudaGetSymbolAddress((void**)&B, g_B);
    cudaGetSymbolAddress((void**)&C, g_C);
    cudaGetSymbolAddress((void**)&M, g_M);
    cudaGetSymbolAddress((void**)&AG, g_AG);

    static bool attr_done = false;
    if (!attr_done) {
        cudaFuncSetAttribute(mlp2_tiled<16>, cudaFuncAttributeMaxDynamicSharedMemorySize,
                             (int)MLP_SMEM);
        cudaFuncSetAttribute(mlp2_tiled<64>, cudaFuncAttributeMaxDynamicSharedMemorySize,
                             (int)MLP_SMEM);
        cudaFuncSetAttribute(mlp2_tiled<128>, cudaFuncAttributeMaxDynamicSharedMemorySize,
                             (int)MLP_SMEM);
        attr_done = true;
    }

    auto grid_for = [](int n) { return mini(((long)n + 63) / 64, 4096); };

    // one message-passing layer; node MLP optionally restricted to sel rows.
    // AG zeroing is fused into the message-MLP epilogue.
    auto mp = [&](int l, const float* hin, float* hout, const int* s, const int* r,
                  int Ecnt, int n, const float* skip, const int* sel, int nout) {
        mlp2_tiled<64><<<grid_for(n), 256, MLP_SMEM>>>(
            hin, nullptr, nullptr, Wm1 + (size_t)l * D * D, bm1 + (size_t)l * D,
            Wm2 + (size_t)l * D * D, bm2 + (size_t)l * D, nullptr, M, AG, n);
        long E16 = (long)Ecnt * 16;
        scatter_kernel<<<mini((E16 + 255) / 256, 8192), 256>>>(M, s, r, AG, E16);
        mlp2_tiled<128><<<grid_for(nout), 256, MLP_SMEM>>>(
            hin, AG, sel, Wn1 + (size_t)l * 128 * D, bn1 + (size_t)l * D,
            Wn2 + (size_t)l * D * D, bn2 + (size_t)l * D, skip, hout, nullptr, nout);
    };

    // encode
    mlp2_tiled<16><<<grid_for(N), 256, MLP_SMEM>>>(
        x, nullptr, nullptr, We1, be1, We2, be2, nullptr, A, nullptr, N);
    // two fine MP layers
    mp(0, A, B, s_f, r_f, E, N, nullptr, nullptr, N);
    mp(1, B, C, s_f, r_f, E, N, nullptr, nullptr, N);
    // skip = C
    // downsample: gather h[uppool], MP on ds graph, node MLP only on downpool rows
    gather_kernel<<<(N * 16 + 511) / 512, 512>>>(C, uppool, A, N);
    mp(2, A, B, s_ds, r_ds, EDS, N, nullptr, downpool, NP);   // B = hp [NP]
    // bottleneck
    mp(3, B, A, s_p, r_p, EP, NP, nullptr, nullptr, NP);
    mp(4, A, B, s_p, r_p, EP, NP, nullptr, nullptr, NP);
    // upsample path: gather by downpool, MP on upsampling graph
    gather_kernel<<<(NP * 16 + 511) / 512, 512>>>(B, downpool, A, NP);
    mp(5, A, B, s_us, r_us, EUS, NP, nullptr, nullptr, NP);
    // scatter back to fine level via uppool gather
    gather_kernel<<<(N * 16 + 511) / 512, 512>>>(B, uppool, A, N);
    // decode MP layers with skip connections
    mp(6, A, B, s_f, r_f, E, N, C, nullptr, N);
    mp(7, B, A, s_f, r_f, E, N, C, nullptr, N);
    // decode head
    decode_kernel<<<mini(((long)N + 7) / 8, 4096), 512>>>(A, Wd1, bd1, Wd2, bd2, out, N);
}